// round 16
// baseline (speedup 1.0000x reference)
#include <cuda_runtime.h>

// RWKV WKV single-pass warp-scan, v9: v8 + conversion hoisted to stage phase.
//   a_t = d_t a_{t-1} + ek_t v_t ; b_t = d_t b_{t-1} + ek_t
//   out = sigmoid(r) * a/(b+eps),  d = exp(-exp(w)), ek = exp(k)
//
// Stage stores CONVERTED operands (d, ek, ek*v) so all MUFU exps run in the
// prefetch window (overlapping LDG latency) instead of the barrier-bounded
// scan phase. Geometry identical to v8 (114.7us): CBLK=32 (128B runs),
// TTILE=64, 512 thr, segmented serial-4 width-16 KS scan, 1 barrier/iter,
// pipelined readback, r never staged.

#define B_      8
#define T_      4096
#define C_      1024
#define CBLK    32
#define TTILE   64
#define NITER   (T_ / TTILE)      // 64
#define THREADS 512
#define SROW    68                // mult of 4 (16B-aligned rows) + skew
#define REGF    (CBLK * SROW)     // 2176 floats per region
#define SMEMB   (8 * REGF * 4)    // d,e,x,so x 2 buffers = 69632 B
#define WKV_EPS 1e-6f

// v8-verified skewed transpose address (conflict-free all three patterns).
__device__ __forceinline__ int saddr(int ch, int t) {
    return ch * SROW + ((t + 4 * (ch >> 2)) & 63);
}

__global__ void __launch_bounds__(THREADS, 2)
wkv_scan9(const float4* __restrict__ r, const float4* __restrict__ w,
          const float4* __restrict__ k, const float4* __restrict__ v,
          float4* __restrict__ out) {
    extern __shared__ float S[];

    const int tid  = threadIdx.x;
    const int lane = tid & 31;
    const int wid  = tid >> 5;    // 0..15
    const int seg  = lane >> 4;   // 0/1: which of the warp's 2 channels
    const int sl   = lane & 15;   // lane within segment
    const int cl4  = tid & 7;     // float4 column (8 x 16B = 128B run)
    const int tl   = tid >> 3;    // 0..63: one t-row per thread (load/store)

    const int b  = blockIdx.x >> 5;               // 8 batches
    const int c0 = (blockIdx.x & 31) * CBLK;      // 32 channel blocks
    const int rowF4 = C_ / 4;                     // 256 float4 per time row
    const int gco   = (b * T_) * rowF4 + (c0 >> 2) + cl4;

    const int chS = 2 * wid + seg;                // scan channel
    const int pS  = saddr(chS, 4 * sl);           // 16B-aligned

    // Prefetch tile 0 (raw w,k,v).
    float4 pw = __ldcs(&w[gco + tl * rowF4]);
    float4 pk = __ldcs(&k[gco + tl * rowF4]);
    float4 pv = __ldcs(&v[gco + tl * rowF4]);
    float4 prPrev;

    float aC = 0.f, bC = 0.f;     // per-lane channel carry (segment-uniform)

    for (int it = 0; it < NITER; ++it) {
        const int bf = it & 1;
        float* sd = S + (0 + bf) * REGF;   // decay d
        float* se = S + (2 + bf) * REGF;   // ek
        float* sx = S + (4 + bf) * REGF;   // ek*v
        float* so = S + (6 + bf) * REGF;
        float* soPrev = S + (6 + (1 - bf)) * REGF;

        // ---- convert + stage current tile (transposed, skewed) ----
        // All MUFU exps happen here, overlapped with LDG latency.
#pragma unroll
        for (int j = 0; j < 4; ++j) {
            const int a = saddr(4 * cl4 + j, tl);
            const float dd = __expf(-__expf(((const float*)&pw)[j]));
            const float ek = __expf(((const float*)&pk)[j]);
            sd[a] = dd;
            se[a] = ek;
            sx[a] = ek * ((const float*)&pv)[j];
        }

        // ---- prefetch: r for THIS tile, w/k/v for the next ----
        float4 pr = __ldcs(&r[gco + (it * TTILE + tl) * rowF4]);
        if (it + 1 < NITER) {
            const int g = gco + ((it + 1) * TTILE + tl) * rowF4;
            pw = __ldcs(&w[g]);  pk = __ldcs(&k[g]);  pv = __ldcs(&v[g]);
        }
        __syncthreads();   // single barrier per iteration

        // ---- segmented serial-4 scan (one channel per 16-lane segment) ----
        {
            const float4 d4 = *(const float4*)&sd[pS];
            const float4 e4 = *(const float4*)&se[pS];
            const float4 x4 = *(const float4*)&sx[pS];
            const float* d = (const float*)&d4;
            const float* e = (const float*)&e4;
            const float* x = (const float*)&x4;

            // lane-local composition of 4 steps (pairwise tree)
            const float D01 = d[0] * d[1];
            const float A01 = fmaf(x[0], d[1], x[1]);
            const float B01 = fmaf(e[0], d[1], e[1]);
            const float D23 = d[2] * d[3];
            const float A23 = fmaf(x[2], d[3], x[3]);
            const float B23 = fmaf(e[2], d[3], e[3]);
            float D  = D01 * D23;
            float A  = fmaf(A01, D23, A23);
            float Bv = fmaf(B01, D23, B23);

            // width-16 inclusive Kogge-Stone over lane aggregates
#pragma unroll
            for (int s = 1; s < 16; s <<= 1) {
                const float Dp = __shfl_up_sync(0xffffffffu, D, s, 16);
                const float Ap = __shfl_up_sync(0xffffffffu, A, s, 16);
                const float Bp = __shfl_up_sync(0xffffffffu, Bv, s, 16);
                if (sl >= s) {
                    A  = fmaf(Ap, D, A);
                    Bv = fmaf(Bp, D, Bv);
                    D *= Dp;
                }
            }
            // exclusive prefix for this lane (within segment)
            float Dx = __shfl_up_sync(0xffffffffu, D, 1, 16);
            float Ax = __shfl_up_sync(0xffffffffu, A, 1, 16);
            float Bx = __shfl_up_sync(0xffffffffu, Bv, 1, 16);
            if (sl == 0) { Dx = 1.f; Ax = 0.f; Bx = 0.f; }
            float ain = fmaf(aC, Dx, Ax);
            float bin = fmaf(bC, Dx, Bx);

            // carry update from segment lane 15 inclusive aggregate
            const float D15 = __shfl_sync(0xffffffffu, D, 15, 16);
            const float A15 = __shfl_sync(0xffffffffu, A, 15, 16);
            const float B15 = __shfl_sync(0xffffffffu, Bv, 15, 16);
            aC = fmaf(aC, D15, A15);
            bC = fmaf(bC, D15, B15);

            // replay 4 local steps, emit a/(b+eps) as one STS.128
            float4 o4;
#pragma unroll
            for (int i = 0; i < 4; ++i) {
                ain = fmaf(ain, d[i], x[i]);
                bin = fmaf(bin, d[i], e[i]);
                ((float*)&o4)[i] = __fdividef(ain, bin + WKV_EPS);
            }
            *(float4*)&so[pS] = o4;
        }

        // ---- pipelined readback of tile it-1 (other buffer; no barrier) ----
        if (it > 0) {
            float4 o;
#pragma unroll
            for (int j = 0; j < 4; ++j)
                ((float*)&o)[j] = soPrev[saddr(4 * cl4 + j, tl)];
            o.x = __fdividef(o.x, 1.f + __expf(-prPrev.x));
            o.y = __fdividef(o.y, 1.f + __expf(-prPrev.y));
            o.z = __fdividef(o.z, 1.f + __expf(-prPrev.z));
            o.w = __fdividef(o.w, 1.f + __expf(-prPrev.w));
            __stcs(&out[gco + ((it - 1) * TTILE + tl) * rowF4], o);
        }
        prPrev = pr;
    }

    // ---- final readback: tile NITER-1 lives in buffer (NITER-1)&1 ----
    __syncthreads();
    {
        float* soLast = S + (6 + ((NITER - 1) & 1)) * REGF;
        float4 o;
#pragma unroll
        for (int j = 0; j < 4; ++j)
            ((float*)&o)[j] = soLast[saddr(4 * cl4 + j, tl)];
        o.x = __fdividef(o.x, 1.f + __expf(-prPrev.x));
        o.y = __fdividef(o.y, 1.f + __expf(-prPrev.y));
        o.z = __fdividef(o.z, 1.f + __expf(-prPrev.z));
        o.w = __fdividef(o.w, 1.f + __expf(-prPrev.w));
        __stcs(&out[gco + ((NITER - 1) * TTILE + tl) * rowF4], o);
    }
}

extern "C" void kernel_launch(void* const* d_in, const int* in_sizes, int n_in,
                              void* d_out, int out_size) {
    const float4* r = (const float4*)d_in[0];
    const float4* w = (const float4*)d_in[1];
    const float4* k = (const float4*)d_in[2];
    const float4* v = (const float4*)d_in[3];
    float4* o = (float4*)d_out;

    cudaFuncSetAttribute(wkv_scan9,
                         cudaFuncAttributeMaxDynamicSharedMemorySize, SMEMB);
    const int grid = B_ * (C_ / CBLK);    // 256 CTAs
    wkv_scan9<<<grid, THREADS, SMEMB>>>(r, w, k, v, o);
}